// round 17
// baseline (speedup 1.0000x reference)
#include <cuda_runtime.h>

#define B    16
#define C    32
#define T    16384
#define NL   30
#define OFF  3069
#define TOUT (T - OFF)   // 13315
#define NCH  256
#define TT2  64          // skip j-tile (doubled: 16 LDS.128 feed 32 FMA2)
#define TT3  64          // head j-tile (doubled, single reused smem buffer)
#define LT   128         // layer time tile
#define KH   240         // skip k-rows per smem stage (4 stages of 240)

typedef unsigned long long u64;

// Packed f32x2 helpers (Blackwell): 2 fp32 FMAs per issue slot, .rn rounding
#define PACK2(dst, lo, hi) \
    asm("mov.b64 %0, {%1, %2};" : "=l"(dst) : "f"(lo), "f"(hi))
#define UNPACK2(lo, hi, src) \
    asm("mov.b64 {%0, %1}, %2;" : "=f"(lo), "=f"(hi) : "l"(src))
#define FMA2(acc, a, b) \
    asm("fma.rn.f32x2 %0, %1, %2, %0;" : "+l"(acc) : "l"(a), "l"(b))
#define ADD2(dst, a, b) \
    asm("add.rn.f32x2 %0, %1, %2;" : "=l"(dst) : "l"(a), "l"(b))

// HW tanh (MUFU.TANH, 1 instruction). sig(g) = 0.5*(1+tanh(g/2)).
__device__ __forceinline__ float tanh_hw(float x) {
    float r;
    asm("tanh.approx.f32 %0, %1;" : "=f"(r) : "f"(x));
    return r;
}
__device__ __forceinline__ float gate_hw(float f, float g) {
    return tanh_hw(f) * (0.5f * tanh_hw(0.5f * g) + 0.5f);
}

// Scratch (device globals). CRITICAL RULE (learned R3-R12): these symbols must
// NEVER be passed as kernel launch arguments from host code — host-side &sym is
// a host shadow address; on-device deref triggers HMM migration (512MB device
// mem delta -> harness rule trip). Reference them ONLY inside device code.
__device__ float g_x[2][(size_t)B * C * T];          //  64 MB ping-pong residual stream
__device__ float g_h[(size_t)NL * B * C * T];        // ~1  GB per-layer gated outputs
__device__ float g_skip[(size_t)B * NCH * TOUT];     // 218 MB relu(skip-sum)
__device__ float g_swT[(size_t)NL * C * NCH];        // skip_w transposed [l*C+c][co]
__device__ float g_w1T[(size_t)NCH * NCH];           // end1_w transposed [k][co]
__device__ float g_w2T[(size_t)NCH * NCH];           // end2_w transposed [k][co]

// ---------------------------------------------------------------------------
// Weight transposes (one-shot, trivial)
// ---------------------------------------------------------------------------
__global__ void transpose_sw_kernel(const float* __restrict__ sw) {
    int idx = blockIdx.x * 256 + threadIdx.x;        // over NL*NCH*C, sw[l][co][c]
    if (idx >= NL * NCH * C) return;
    int c  = idx & 31;
    int co = (idx >> 5) & 255;
    int l  = idx >> 13;
    g_swT[((size_t)l * C + c) * NCH + co] = sw[idx];
}

__global__ void transpose_w_kernel(const float* __restrict__ w, int which) {
    int idx = blockIdx.x * 256 + threadIdx.x;        // over NCH*NCH, w[co][k]
    if (idx >= NCH * NCH) return;
    int k  = idx & 255;
    int co = idx >> 8;
    float* dst = which ? g_w2T : g_w1T;
    dst[(size_t)k * NCH + co] = w[idx];
}

// ---------------------------------------------------------------------------
// 1x1 causal conv: x0[b][c][t] = cw[c]*y[b][t] + cb[c]
// ---------------------------------------------------------------------------
__global__ void causal_kernel(const float* __restrict__ y,
                              const float* __restrict__ cw,
                              const float* __restrict__ cb) {
    int idx = blockIdx.x * 256 + threadIdx.x;         // over B*C*T
    if (idx >= B * C * T) return;
    int t = idx & (T - 1);
    int c = (idx >> 14) & 31;
    int b = idx >> 19;
    g_x[0][idx] = cw[c] * y[b * T + t] + cb[c];
}

// ---------------------------------------------------------------------------
// One WaveNet layer, 128-t tile, 256 threads (R16-proven, unchanged).
// ---------------------------------------------------------------------------
__global__ __launch_bounds__(256) void layer_kernel(
    const float* __restrict__ fw, const float* __restrict__ gw,
    const float* __restrict__ rw, int layer, int ping, int d, int lo) {
    extern __shared__ float sm[];
    u64*   s_fw2 = (u64*)sm;                          // [C*C*2] u64 = 16KB
    u64*   s_gw2 = (u64*)(sm + 4096);                 // 16KB
    u64*   s_rw2 = (u64*)(sm + 8192);                 // [C*C] u64 = 8KB
    float* xs    = sm + 10240;                        // C*LT (16KB)
    float* xd    = xs + C * LT;                       // 16KB
    float* hs    = xd + C * LT;                       // 16KB -> total 88KB

    const float* xin  = g_x[ping];
    float*       xout = g_x[ping ^ 1];
    float*       hout = g_h + (size_t)layer * B * C * T;

    int b   = blockIdx.y;
    int tid = threadIdx.x;
    int t0  = (lo & ~(LT - 1)) + blockIdx.x * LT;     // 128-aligned; t0 <= T-128

    // Stage weights: duplicate each scalar into a packed (w,w) u64.
    for (int i = tid; i < C * C; i += 256) {
        float2 wf = ((const float2*)fw)[i];
        float2 wg = ((const float2*)gw)[i];
        float  wr = rw[i];
        u64 p;
        PACK2(p, wf.x, wf.x);  s_fw2[2 * i]     = p;
        PACK2(p, wf.y, wf.y);  s_fw2[2 * i + 1] = p;
        PACK2(p, wg.x, wg.x);  s_gw2[2 * i]     = p;
        PACK2(p, wg.y, wg.y);  s_gw2[2 * i + 1] = p;
        PACK2(p, wr, wr);      s_rw2[i]         = p;
    }

    const float* xb = xin + (size_t)b * C * T;
    for (int i = tid; i < C * LT; i += 256) {
        int c = i >> 7, tt = i & (LT - 1);
        int t = t0 + tt;
        bool v = (t >= lo);                           // t < T always (t0 <= T-128)
        xs[i] = v ? xb[c * T + t]     : 0.f;
        xd[i] = v ? xb[c * T + t - d] : 0.f;
    }
    __syncthreads();

    // ---- phase 1: thread = (channels c0,c1) x (8 time steps), packed f32x2
    int cp  = tid >> 4;                               // 0..15
    int c0  = cp * 2, c1 = c0 + 1;
    int ttb = (tid & 15) * 8;
    u64 a_f0[4], a_g0[4], a_f1[4], a_g1[4];
#pragma unroll
    for (int q = 0; q < 4; q++) { a_f0[q]=0; a_g0[q]=0; a_f1[q]=0; a_g1[q]=0; }
#pragma unroll 8
    for (int ci = 0; ci < C; ci++) {
        ulonglong2 wf0 = *(const ulonglong2*)&s_fw2[(c0 * C + ci) * 2];
        ulonglong2 wf1 = *(const ulonglong2*)&s_fw2[(c1 * C + ci) * 2];
        ulonglong2 wg0 = *(const ulonglong2*)&s_gw2[(c0 * C + ci) * 2];
        ulonglong2 wg1 = *(const ulonglong2*)&s_gw2[(c1 * C + ci) * 2];
        const u64* dp = (const u64*)&xd[ci * LT + ttb];
        const u64* sp = (const u64*)&xs[ci * LT + ttb];
#pragma unroll
        for (int q = 0; q < 4; q++) {
            u64 dv = dp[q], sv = sp[q];
            FMA2(a_f0[q], wf0.x, dv);  FMA2(a_f0[q], wf0.y, sv);
            FMA2(a_g0[q], wg0.x, dv);  FMA2(a_g0[q], wg0.y, sv);
            FMA2(a_f1[q], wf1.x, dv);  FMA2(a_f1[q], wf1.y, sv);
            FMA2(a_g1[q], wg1.x, dv);  FMA2(a_g1[q], wg1.y, sv);
        }
    }
    float af0[8], ag0[8], af1[8], ag1[8];
#pragma unroll
    for (int q = 0; q < 4; q++) {
        UNPACK2(af0[2*q], af0[2*q+1], a_f0[q]);
        UNPACK2(ag0[2*q], ag0[2*q+1], a_g0[q]);
        UNPACK2(af1[2*q], af1[2*q+1], a_f1[q]);
        UNPACK2(ag1[2*q], ag1[2*q+1], a_g1[q]);
    }
    float hv0[8], hv1[8];
#pragma unroll
    for (int q = 0; q < 8; q++) {
        hv0[q] = gate_hw(af0[q], ag0[q]);
        hv1[q] = gate_hw(af1[q], ag1[q]);
    }
#pragma unroll
    for (int q = 0; q < 8; q++) {
        hs[c0 * LT + ttb + q] = hv0[q];
        hs[c1 * LT + ttb + q] = hv1[q];
    }
    {
        // global h store only where skip reads it (t >= OFF); t < T always.
        float* h0 = hout + (size_t)b * C * T + (size_t)c0 * T;
        float* h1 = hout + (size_t)b * C * T + (size_t)c1 * T;
        int tb = t0 + ttb;
        if (tb >= OFF) {
            *(float4*)&h0[tb]     = *(float4*)&hv0[0];
            *(float4*)&h0[tb + 4] = *(float4*)&hv0[4];
            *(float4*)&h1[tb]     = *(float4*)&hv1[0];
            *(float4*)&h1[tb + 4] = *(float4*)&hv1[4];
        } else if (tb + 7 >= OFF) {
#pragma unroll
            for (int q = 0; q < 8; q++) {
                int t = tb + q;
                if (t >= OFF) { h0[t] = hv0[q]; h1[t] = hv1[q]; }
            }
        }
    }
    __syncthreads();

    // ---- phase 2: residual conv; thread = (8 out-ch, 2 packed t)
    {
        int grp  = tid >> 6;                          // 0..3 -> co0 = grp*8
        int co0  = grp * 8;
        int tl2  = tid & 63;
        int tt   = tl2 * 2;                           // local t (even)
        int tg   = t0 + tt;

        u64 h2[C];
#pragma unroll
        for (int ci = 0; ci < C; ci++)
            h2[ci] = *(const u64*)&hs[ci * LT + tt];

        float* xob = xout + (size_t)b * C * T;
        bool full = (tg >= lo);
        bool part = (!full) && (tg + 1 >= lo);
#pragma unroll
        for (int k = 0; k < 8; k++) {
            int co = co0 + k;
            u64 acc2 = 0;
#pragma unroll
            for (int c2 = 0; c2 < C; c2 += 2) {
                ulonglong2 w2 = *(const ulonglong2*)&s_rw2[co * C + c2];
                FMA2(acc2, w2.x, h2[c2]);
                FMA2(acc2, w2.y, h2[c2 + 1]);
            }
            u64 xv = *(const u64*)&xs[co * LT + tt];
            u64 res;
            ADD2(res, acc2, xv);
            if (full) {
                *(u64*)&xob[co * T + tg] = res;
            } else if (part) {
                float lo_, hi_;
                UNPACK2(lo_, hi_, res);
                xob[co * T + tg + 1] = hi_;
            }
        }
    }
}

// ---------------------------------------------------------------------------
// Fused skip reduction, TT2=64 j-tile: per kk 16 LDS.128 feed 32 FMA2.
// 4 stages of KH=240 rows (60KB smem).
// ---------------------------------------------------------------------------
__global__ __launch_bounds__(256) void skip_kernel() {
    extern __shared__ float hs2[];                    // [KH][TT2] = 60KB
    int b = blockIdx.y, j0 = blockIdx.x * TT2, tid = threadIdx.x;

    int co = tid;
    u64 acc2[TT2 / 2];
#pragma unroll
    for (int q = 0; q < TT2 / 2; q++) acc2[q] = 0;

    const float* wT = g_swT + co;                     // lane-coalesced base

    for (int stage = 0; stage < 4; stage++) {
        for (int i = tid; i < KH * TT2; i += 256) {
            int k  = stage * KH + (i >> 6);
            int tt = i & (TT2 - 1);
            int j  = j0 + tt;
            float v = 0.f;
            if (j < TOUT) {
                int layer = k >> 5, cc = k & 31;
                v = g_h[(((size_t)layer * B + b) * C + cc) * T + OFF + j];
            }
            hs2[i] = v;
        }
        __syncthreads();

        const float* wTh = wT + (size_t)stage * KH * NCH;
#pragma unroll 8
        for (int kk = 0; kk < KH; kk++) {
            float w = __ldg(&wTh[(size_t)kk * NCH]);
            u64 w2;  PACK2(w2, w, w);
            const ulonglong2* hp = (const ulonglong2*)&hs2[kk * TT2];
#pragma unroll
            for (int q = 0; q < TT2 / 4; q++) {
                ulonglong2 hv = hp[q];
                FMA2(acc2[2 * q],     w2, hv.x);
                FMA2(acc2[2 * q + 1], w2, hv.y);
            }
        }
        __syncthreads();
    }

    float* so = g_skip + ((size_t)b * NCH + co) * TOUT;
#pragma unroll
    for (int q = 0; q < TT2 / 2; q++) {
        float lo, hi;
        UNPACK2(lo, hi, acc2[q]);
        int j = j0 + 2 * q;
        if (j     < TOUT) so[j]     = fmaxf(lo, 0.f);
        if (j + 1 < TOUT) so[j + 1] = fmaxf(hi, 0.f);
    }
}

// ---------------------------------------------------------------------------
// Head, TT3=64, SINGLE 64KB buffer reused for relu(skip) then hidden:
// phase-1 reads complete before the sync; results live in registers; then the
// buffer is overwritten with relu(hidden) for phase 2.
// ---------------------------------------------------------------------------
__global__ __launch_bounds__(256) void head_kernel(
    const float* __restrict__ b1, const float* __restrict__ b2,
    float* __restrict__ out) {
    extern __shared__ float ss[];                     // [NCH][TT3] = 64KB
    int b = blockIdx.y, j0 = blockIdx.x * TT3, tid = threadIdx.x;

    for (int i = tid; i < NCH * TT3; i += 256) {
        int k = i >> 6, tt = i & (TT3 - 1);
        int j = j0 + tt;
        ss[i] = (j < TOUT) ? g_skip[((size_t)b * NCH + k) * TOUT + j] : 0.f;
    }
    __syncthreads();

    int co = tid;
    u64 acc2[TT3 / 2];
#pragma unroll
    for (int q = 0; q < TT3 / 2; q++) acc2[q] = 0;
    const float* w1c = g_w1T + co;
#pragma unroll 8
    for (int k = 0; k < NCH; k++) {
        float w = __ldg(&w1c[(size_t)k * NCH]);
        u64 w2;  PACK2(w2, w, w);
        const ulonglong2* sp = (const ulonglong2*)&ss[k * TT3];
#pragma unroll
        for (int q = 0; q < TT3 / 4; q++) {
            ulonglong2 sv = sp[q];
            FMA2(acc2[2 * q],     w2, sv.x);
            FMA2(acc2[2 * q + 1], w2, sv.y);
        }
    }
    float bb1 = b1[co];
    __syncthreads();                                  // all phase-1 reads done

    // overwrite buffer with relu(hidden): row co
    {
        u64* srow = (u64*)&ss[co * TT3];
#pragma unroll
        for (int q = 0; q < TT3 / 2; q++) {
            float lo, hi;
            UNPACK2(lo, hi, acc2[q]);
            u64 p;
            PACK2(p, fmaxf(lo + bb1, 0.f), fmaxf(hi + bb1, 0.f));
            srow[q] = p;
        }
    }
    __syncthreads();

#pragma unroll
    for (int q = 0; q < TT3 / 2; q++) acc2[q] = 0;
    const float* w2c = g_w2T + co;
#pragma unroll 8
    for (int k = 0; k < NCH; k++) {
        float w = __ldg(&w2c[(size_t)k * NCH]);
        u64 w2;  PACK2(w2, w, w);
        const ulonglong2* sp = (const ulonglong2*)&ss[k * TT3];
#pragma unroll
        for (int q = 0; q < TT3 / 4; q++) {
            ulonglong2 sv = sp[q];
            FMA2(acc2[2 * q],     w2, sv.x);
            FMA2(acc2[2 * q + 1], w2, sv.y);
        }
    }
    float bb2 = b2[co];
    float* op = out + ((size_t)b * NCH + co) * TOUT;
#pragma unroll
    for (int q = 0; q < TT3 / 2; q++) {
        float lo, hi;
        UNPACK2(lo, hi, acc2[q]);
        int j = j0 + 2 * q;
        if (j     < TOUT) op[j]     = lo + bb2;
        if (j + 1 < TOUT) op[j + 1] = hi + bb2;
    }
}

// ---------------------------------------------------------------------------
extern "C" void kernel_launch(void* const* d_in, const int* in_sizes, int n_in,
                              void* d_out, int out_size) {
    const float* y   = (const float*)d_in[0];
    const float* cw  = (const float*)d_in[1];
    const float* cb  = (const float*)d_in[2];
    const float* fw  = (const float*)d_in[3];
    const float* gw  = (const float*)d_in[4];
    const float* rw  = (const float*)d_in[5];
    const float* sw  = (const float*)d_in[6];
    const float* e1w = (const float*)d_in[7];
    const float* e1b = (const float*)d_in[8];
    const float* e2w = (const float*)d_in[9];
    const float* e2b = (const float*)d_in[10];
    float* out = (float*)d_out;

    transpose_sw_kernel<<<(NL * NCH * C + 255) / 256, 256>>>(sw);
    transpose_w_kernel<<<(NCH * NCH + 255) / 256, 256>>>(e1w, 0);
    transpose_w_kernel<<<(NCH * NCH + 255) / 256, 256>>>(e2w, 1);

    causal_kernel<<<(B * C * T + 255) / 256, 256>>>(y, cw, cb);

    const int lyr_smem = (10240 + 3 * C * LT) * 4;    // 90,112 B
    cudaFuncSetAttribute(layer_kernel, cudaFuncAttributeMaxDynamicSharedMemorySize,
                         lyr_smem);

    int lin = 0;
    for (int i = 0; i < NL; i++) {
        int d  = 1 << (i % 10);
        int lo = lin + d;                  // first valid output time index
        int tb = lo & ~(LT - 1);
        int tiles = (T - tb + LT - 1) / LT;
        dim3 grid(tiles, B);
        layer_kernel<<<grid, 256, lyr_smem>>>(fw + (size_t)i * C * C * 2,
                                              gw + (size_t)i * C * C * 2,
                                              rw + (size_t)i * C * C,
                                              i, i & 1, d, lo);
        lin = lo;
    }

    const int skip_smem = KH * TT2 * 4;               // 61,440 B
    cudaFuncSetAttribute(skip_kernel, cudaFuncAttributeMaxDynamicSharedMemorySize,
                         skip_smem);
    dim3 gs((TOUT + TT2 - 1) / TT2, B);
    skip_kernel<<<gs, 256, skip_smem>>>();

    const int head_smem = NCH * TT3 * 4;              // 65,536 B
    cudaFuncSetAttribute(head_kernel, cudaFuncAttributeMaxDynamicSharedMemorySize,
                         head_smem);
    dim3 gh((TOUT + TT3 - 1) / TT3, B);
    head_kernel<<<gh, 256, head_smem>>>(e1b, e2b, out);
}